// round 7
// baseline (speedup 1.0000x reference)
#include <cuda_runtime.h>

#define CIN  128
#define PP   784          // 28*28
#define NPIX 3136         // 4*784
typedef unsigned long long ull;

// ---------------- scratch (device globals; no allocation) ----------------
__device__ __align__(16) float g_y1p[2][CIN * NPIX];  // conv1x1 ci-half partials
__device__ __align__(16) float g_s1p[2][CIN * NPIX];  // adder1x1 ci-half partial L1 sums
__device__ __align__(16) float g_p3 [6][CIN * NPIX];  // conv3x3 (kh,ciHalf) partials
__device__ __align__(16) float g_y3 [CIN * NPIX];     // conv3x3 combined
__device__ __align__(16) float g_p4 [6][CIN * NPIX];  // adder3x3 partials (+S)
// transposed weights: [ci][co] (plain float; duplicated at STS time)
__device__ __align__(16) float g_w1t [CIN * CIN];
__device__ __align__(16) float g_wa1t[CIN * CIN];
__device__ __align__(16) float g_w2t [9][CIN * CIN];
__device__ __align__(16) float g_wa2t[9][CIN * CIN];
// BN1 folded params
__device__ float g_sc1[CIN], g_sh1[CIN];

// ---------------- packed f32x2 helpers -----------------------------------
__device__ __forceinline__ ull fma2(ull a, ull b, ull c) {
    ull d; asm("fma.rn.f32x2 %0, %1, %2, %3;" : "=l"(d) : "l"(a), "l"(b), "l"(c)); return d;
}
__device__ __forceinline__ ull add2(ull a, ull b) {
    ull d; asm("add.rn.f32x2 %0, %1, %2;" : "=l"(d) : "l"(a), "l"(b)); return d;
}
#define NEG1X2 0xBF800000BF800000ULL
#define ABSM   0x7FFFFFFF7FFFFFFFULL

// =========================================================================
// kprep: transpose weights; fold BN1.
// =========================================================================
__global__ __launch_bounds__(256) void kprep(const float* __restrict__ w1,
                                             const float* __restrict__ wa1,
                                             const float* __restrict__ w2,
                                             const float* __restrict__ wa2,
                                             const float* __restrict__ g1,
                                             const float* __restrict__ b1,
                                             const float* __restrict__ m1,
                                             const float* __restrict__ v1) {
    int i = blockIdx.x * 256 + threadIdx.x;     // 64 blocks -> 16384
    int ci = i >> 7, co = i & 127;
    g_w1t [ci * CIN + co] = w1 [co * CIN + ci];
    g_wa1t[ci * CIN + co] = wa1[co * CIN + ci];
#pragma unroll
    for (int t = 0; t < 9; t++) {
        g_w2t [t][ci * CIN + co] = w2 [(co * CIN + ci) * 9 + t];
        g_wa2t[t][ci * CIN + co] = wa2[(co * CIN + ci) * 9 + t];
    }
    if (blockIdx.x == 0 && threadIdx.x < CIN) {
        int c = threadIdx.x;
        float sc = g1[c] / sqrtf(v1[c] + 1e-5f);
        g_sc1[c] = sc;
        g_sh1[c] = b1[c] - m1[c] * sc;
    }
}

// =========================================================================
// k1: conv1x1 ci-half partial. grid (2,49,2). CTA 64co x 64px, tile 4x4.
// =========================================================================
__global__ __launch_bounds__(256) void k1_conv1x1(const float* __restrict__ x) {
    __shared__ __align__(16) float  sA[2][16][64];
    __shared__ __align__(16) float2 sW[2][16][64];
    const int tid = threadIdx.x;
    const int col = tid & 15, row = tid >> 4;
    const int coBase = blockIdx.x * 64;
    const int qBase  = blockIdx.y * 64;
    const int ciBase = blockIdx.z * 64;

    ull acc[4][2];
#pragma unroll
    for (int i = 0; i < 4; i++) { acc[i][0] = 0; acc[i][1] = 0; }

    float aReg[4], wReg[4];
    auto ldg = [&](int s) {
        int ci0 = ciBase + (s << 4);
#pragma unroll
        for (int k = 0; k < 4; k++) {
            int e = k * 256 + tid;
            int q = qBase + (e & 63);
            int n = q / PP, p = q - n * PP;
            aReg[k] = x[(n * CIN + ci0 + (e >> 6)) * PP + p];
        }
#pragma unroll
        for (int k = 0; k < 4; k++) {
            int e = k * 256 + tid;
            wReg[k] = g_w1t[(ci0 + (e >> 6)) * CIN + coBase + (e & 63)];
        }
    };
    auto sts = [&](int b) {
#pragma unroll
        for (int k = 0; k < 4; k++) { int e = k * 256 + tid; sA[b][e >> 6][e & 63] = aReg[k]; }
#pragma unroll
        for (int k = 0; k < 4; k++) { int e = k * 256 + tid; sW[b][e >> 6][e & 63] = make_float2(wReg[k], wReg[k]); }
    };

    ldg(0); sts(0); __syncthreads();
    for (int s = 0; s < 4; s++) {
        int b = s & 1;
        if (s < 3) ldg(s + 1);
#pragma unroll
        for (int ci = 0; ci < 16; ci++) {
            ulonglong2 av = *(const ulonglong2*)&sA[b][ci][col * 4];
            ulonglong2 wp = *(const ulonglong2*)&sW[b][ci][row * 4];
            ulonglong2 wq = *(const ulonglong2*)&sW[b][ci][row * 4 + 2];
            acc[0][0] = fma2(wp.x, av.x, acc[0][0]); acc[0][1] = fma2(wp.x, av.y, acc[0][1]);
            acc[1][0] = fma2(wp.y, av.x, acc[1][0]); acc[1][1] = fma2(wp.y, av.y, acc[1][1]);
            acc[2][0] = fma2(wq.x, av.x, acc[2][0]); acc[2][1] = fma2(wq.x, av.y, acc[2][1]);
            acc[3][0] = fma2(wq.y, av.x, acc[3][0]); acc[3][1] = fma2(wq.y, av.y, acc[3][1]);
        }
        if (s < 3) sts(b ^ 1);
        __syncthreads();
    }
    const int q = qBase + col * 4;
    float* __restrict__ out = g_y1p[blockIdx.z];
#pragma unroll
    for (int i = 0; i < 4; i++) {
        int co = coBase + row * 4 + i;
        *(ull*)&out[co * NPIX + q]     = acc[i][0];
        *(ull*)&out[co * NPIX + q + 2] = acc[i][1];
    }
}

// =========================================================================
// k2: adder1x1 ci-half partial L1 sums. A = y1p[0]+y1p[1] at staging.
// =========================================================================
__global__ __launch_bounds__(256) void k2_adder1x1() {
    __shared__ __align__(16) float  sA[2][16][64];
    __shared__ __align__(16) float2 sW[2][16][64];
    const int tid = threadIdx.x;
    const int col = tid & 15, row = tid >> 4;
    const int coBase = blockIdx.x * 64;
    const int qBase  = blockIdx.y * 64;
    const int ciBase = blockIdx.z * 64;

    ull acc[4][2];
#pragma unroll
    for (int i = 0; i < 4; i++) { acc[i][0] = 0; acc[i][1] = 0; }

    float aReg[4], wReg[4];
    auto ldg = [&](int s) {
        int ci0 = ciBase + (s << 4);
#pragma unroll
        for (int k = 0; k < 4; k++) {
            int e = k * 256 + tid;
            int off = (ci0 + (e >> 6)) * NPIX + qBase + (e & 63);
            aReg[k] = g_y1p[0][off] + g_y1p[1][off];
        }
#pragma unroll
        for (int k = 0; k < 4; k++) {
            int e = k * 256 + tid;
            wReg[k] = g_wa1t[(ci0 + (e >> 6)) * CIN + coBase + (e & 63)];
        }
    };
    auto sts = [&](int b) {
#pragma unroll
        for (int k = 0; k < 4; k++) { int e = k * 256 + tid; sA[b][e >> 6][e & 63] = aReg[k]; }
#pragma unroll
        for (int k = 0; k < 4; k++) { int e = k * 256 + tid; sW[b][e >> 6][e & 63] = make_float2(wReg[k], wReg[k]); }
    };

    ldg(0); sts(0); __syncthreads();
    for (int s = 0; s < 4; s++) {
        int b = s & 1;
        if (s < 3) ldg(s + 1);
#pragma unroll
        for (int ci = 0; ci < 16; ci++) {
            ulonglong2 av = *(const ulonglong2*)&sA[b][ci][col * 4];
            ulonglong2 wp = *(const ulonglong2*)&sW[b][ci][row * 4];
            ulonglong2 wq = *(const ulonglong2*)&sW[b][ci][row * 4 + 2];
            acc[0][0] = add2(acc[0][0], fma2(wp.x, NEG1X2, av.x) & ABSM);
            acc[0][1] = add2(acc[0][1], fma2(wp.x, NEG1X2, av.y) & ABSM);
            acc[1][0] = add2(acc[1][0], fma2(wp.y, NEG1X2, av.x) & ABSM);
            acc[1][1] = add2(acc[1][1], fma2(wp.y, NEG1X2, av.y) & ABSM);
            acc[2][0] = add2(acc[2][0], fma2(wq.x, NEG1X2, av.x) & ABSM);
            acc[2][1] = add2(acc[2][1], fma2(wq.x, NEG1X2, av.y) & ABSM);
            acc[3][0] = add2(acc[3][0], fma2(wq.y, NEG1X2, av.x) & ABSM);
            acc[3][1] = add2(acc[3][1], fma2(wq.y, NEG1X2, av.y) & ABSM);
        }
        if (s < 3) sts(b ^ 1);
        __syncthreads();
    }
    const int q = qBase + col * 4;
    float* __restrict__ out = g_s1p[blockIdx.z];
#pragma unroll
    for (int i = 0; i < 4; i++) {
        int co = coBase + row * 4 + i;
        *(ull*)&out[co * NPIX + q]     = acc[i][0];
        *(ull*)&out[co * NPIX + q + 2] = acc[i][1];
    }
}

// =========================================================================
// k3/k4: 3x3 conv / adder. CTA 128co x 64px, 256 thr, thread tile 4co x 8px.
// col = tid&7 (8 px), row = tid>>3 (4 co). Warp: A LDS = 8 distinct lines
// (1 wf/LDS.128), W LDS = 4 distinct (broadcast). grid (49, 6), y=kh*2+ciHalf.
// Conv fuses BN1+ReLU of adder1x1 partials into A staging.
// =========================================================================
template <bool ADDER>
__global__ __launch_bounds__(256) void k3x3() {
    __shared__ __align__(16) float  sA[2][16][64];
    __shared__ __align__(16) float2 sW[2][16][128];
    __shared__ int sIdx[3][64];
    __shared__ float2 sBN[64];

    const int tid = threadIdx.x;
    const int col = tid & 7, row = tid >> 3;
    const int qBase  = blockIdx.x * 64;
    const int kh     = blockIdx.y >> 1;
    const int ciBase = (blockIdx.y & 1) * 64;

    if (tid < 64) {
        int q = qBase + tid;
        int n = q / PP, p = q - n * PP;
        int h = p / 28, w = p - h * 28;
#pragma unroll
        for (int kw = 0; kw < 3; kw++) {
            int hh = h + kh - 1, ww = w + kw - 1;
            sIdx[kw][tid] = ((unsigned)hh < 28u && (unsigned)ww < 28u)
                          ? (n * PP + hh * 28 + ww) : -1;
        }
        if (!ADDER) sBN[tid] = make_float2(g_sc1[ciBase + tid], g_sh1[ciBase + tid]);
    }
    __syncthreads();

    ull acc[4][4];
#pragma unroll
    for (int i = 0; i < 4; i++)
#pragma unroll
        for (int j = 0; j < 4; j++) acc[i][j] = 0;

    const float* __restrict__ wsrc = ADDER ? &g_wa2t[0][0] : &g_w2t[0][0];

    float aReg[4], wReg[8];
    auto ldg = [&](int s) {
        int kw = s >> 2, ciOff = (s & 3) << 4;
#pragma unroll
        for (int k = 0; k < 4; k++) {               // A: 64px x 16ci / 256thr
            int e = k * 256 + tid;
            int ciL = ciOff + (e >> 6);             // 0..63 within half
            int idx = sIdx[kw][e & 63];
            float v = 0.f;
            if (idx >= 0) {
                int off = (ciBase + ciL) * NPIX + idx;
                if (ADDER) {
                    v = g_y3[off];
                } else {
                    float ssum = g_s1p[0][off] + g_s1p[1][off];
                    float2 bn = sBN[ciL];
                    v = fmaxf(fmaf(-ssum, bn.x, bn.y), 0.f);
                }
            }
            aReg[k] = v;
        }
        const float* __restrict__ wslice = wsrc + (kh * 3 + kw) * (CIN * CIN);
#pragma unroll
        for (int k = 0; k < 8; k++) {               // W: 128co x 16ci / 256thr
            int e = k * 256 + tid;
            wReg[k] = wslice[(ciBase + ciOff + (e >> 7)) * CIN + (e & 127)];
        }
    };
    auto sts = [&](int b) {
#pragma unroll
        for (int k = 0; k < 4; k++) { int e = k * 256 + tid; sA[b][e >> 6][e & 63] = aReg[k]; }
#pragma unroll
        for (int k = 0; k < 8; k++) { int e = k * 256 + tid; sW[b][e >> 7][e & 127] = make_float2(wReg[k], wReg[k]); }
    };

    ldg(0); sts(0); __syncthreads();
    for (int s = 0; s < 12; s++) {
        int b = s & 1;
        if (s < 11) ldg(s + 1);
#pragma unroll
        for (int ci = 0; ci < 16; ci++) {
            ulonglong2 a01 = *(const ulonglong2*)&sA[b][ci][col * 8];
            ulonglong2 a23 = *(const ulonglong2*)&sA[b][ci][col * 8 + 4];
            ulonglong2 w01 = *(const ulonglong2*)&sW[b][ci][row * 4];
            ulonglong2 w23 = *(const ulonglong2*)&sW[b][ci][row * 4 + 2];
            if (ADDER) {
                acc[0][0] = add2(acc[0][0], fma2(w01.x, NEG1X2, a01.x) & ABSM);
                acc[0][1] = add2(acc[0][1], fma2(w01.x, NEG1X2, a01.y) & ABSM);
                acc[0][2] = add2(acc[0][2], fma2(w01.x, NEG1X2, a23.x) & ABSM);
                acc[0][3] = add2(acc[0][3], fma2(w01.x, NEG1X2, a23.y) & ABSM);
                acc[1][0] = add2(acc[1][0], fma2(w01.y, NEG1X2, a01.x) & ABSM);
                acc[1][1] = add2(acc[1][1], fma2(w01.y, NEG1X2, a01.y) & ABSM);
                acc[1][2] = add2(acc[1][2], fma2(w01.y, NEG1X2, a23.x) & ABSM);
                acc[1][3] = add2(acc[1][3], fma2(w01.y, NEG1X2, a23.y) & ABSM);
                acc[2][0] = add2(acc[2][0], fma2(w23.x, NEG1X2, a01.x) & ABSM);
                acc[2][1] = add2(acc[2][1], fma2(w23.x, NEG1X2, a01.y) & ABSM);
                acc[2][2] = add2(acc[2][2], fma2(w23.x, NEG1X2, a23.x) & ABSM);
                acc[2][3] = add2(acc[2][3], fma2(w23.x, NEG1X2, a23.y) & ABSM);
                acc[3][0] = add2(acc[3][0], fma2(w23.y, NEG1X2, a01.x) & ABSM);
                acc[3][1] = add2(acc[3][1], fma2(w23.y, NEG1X2, a01.y) & ABSM);
                acc[3][2] = add2(acc[3][2], fma2(w23.y, NEG1X2, a23.x) & ABSM);
                acc[3][3] = add2(acc[3][3], fma2(w23.y, NEG1X2, a23.y) & ABSM);
            } else {
                acc[0][0] = fma2(w01.x, a01.x, acc[0][0]);
                acc[0][1] = fma2(w01.x, a01.y, acc[0][1]);
                acc[0][2] = fma2(w01.x, a23.x, acc[0][2]);
                acc[0][3] = fma2(w01.x, a23.y, acc[0][3]);
                acc[1][0] = fma2(w01.y, a01.x, acc[1][0]);
                acc[1][1] = fma2(w01.y, a01.y, acc[1][1]);
                acc[1][2] = fma2(w01.y, a23.x, acc[1][2]);
                acc[1][3] = fma2(w01.y, a23.y, acc[1][3]);
                acc[2][0] = fma2(w23.x, a01.x, acc[2][0]);
                acc[2][1] = fma2(w23.x, a01.y, acc[2][1]);
                acc[2][2] = fma2(w23.x, a23.x, acc[2][2]);
                acc[2][3] = fma2(w23.x, a23.y, acc[2][3]);
                acc[3][0] = fma2(w23.y, a01.x, acc[3][0]);
                acc[3][1] = fma2(w23.y, a01.y, acc[3][1]);
                acc[3][2] = fma2(w23.y, a23.x, acc[3][2]);
                acc[3][3] = fma2(w23.y, a23.y, acc[3][3]);
            }
        }
        if (s < 11) sts(b ^ 1);
        __syncthreads();
    }
    const int q = qBase + col * 8;
    float* __restrict__ out = ADDER ? g_p4[blockIdx.y] : g_p3[blockIdx.y];
#pragma unroll
    for (int i = 0; i < 4; i++) {
        int co = row * 4 + i;
#pragma unroll
        for (int j = 0; j < 4; j++)
            *(ull*)&out[co * NPIX + q + 2 * j] = acc[i][j];
    }
}

// ky: y3 = sum of 6 conv partials. 784 blocks x 128 thr, one float4 each.
__global__ __launch_bounds__(128) void ky() {
    int i = (blockIdx.x * 128 + threadIdx.x) * 4;
    float4 s = *(const float4*)&g_p3[0][i];
#pragma unroll
    for (int t = 1; t < 6; t++) {
        float4 a = *(const float4*)&g_p3[t][i];
        s.x += a.x; s.y += a.y; s.z += a.z; s.w += a.w;
    }
    *(float4*)&g_y3[i] = s;
}

// Epilogue: out = relu( relu(bn2(-S)) + x ), S = sum of 6 adder partials.
__device__ __forceinline__ float epi1(float S, float xv, float scale, float shift) {
    float v = fmaxf(fmaf(-S, scale, shift), 0.f);
    return fmaxf(v + xv, 0.f);
}
__global__ __launch_bounds__(128) void kepi(const float* __restrict__ x,
                                             const float* __restrict__ g2,
                                             const float* __restrict__ b2,
                                             const float* __restrict__ m2,
                                             const float* __restrict__ v2,
                                             float* __restrict__ out) {
    int base = (blockIdx.x * 128 + threadIdx.x) * 4;
    int c = base / NPIX;
    int q = base - c * NPIX;
    int n = q / PP, p = q - n * PP;
    float scale = g2[c] / sqrtf(v2[c] + 1e-5f);
    float shift = b2[c] - m2[c] * scale;
    float4 s = *(const float4*)&g_p4[0][base];
#pragma unroll
    for (int t = 1; t < 6; t++) {
        float4 a = *(const float4*)&g_p4[t][base];
        s.x += a.x; s.y += a.y; s.z += a.z; s.w += a.w;
    }
    int xi = (n * CIN + c) * PP + p;
    float4 xr = *(const float4*)&x[xi];
    float4 r;
    r.x = epi1(s.x, xr.x, scale, shift);
    r.y = epi1(s.y, xr.y, scale, shift);
    r.z = epi1(s.z, xr.z, scale, shift);
    r.w = epi1(s.w, xr.w, scale, shift);
    *(float4*)&out[xi] = r;
}

// =========================================================================
extern "C" void kernel_launch(void* const* d_in, const int* in_sizes, int n_in,
                              void* d_out, int out_size) {
    const float* x   = (const float*)d_in[0];
    const float* w1  = (const float*)d_in[1];
    const float* wa1 = (const float*)d_in[2];
    const float* g1  = (const float*)d_in[3];
    const float* b1  = (const float*)d_in[4];
    const float* m1  = (const float*)d_in[5];
    const float* v1  = (const float*)d_in[6];
    const float* w2  = (const float*)d_in[7];
    const float* wa2 = (const float*)d_in[8];
    const float* g2  = (const float*)d_in[9];
    const float* b2  = (const float*)d_in[10];
    const float* m2  = (const float*)d_in[11];
    const float* v2  = (const float*)d_in[12];
    float* out = (float*)d_out;

    kprep       <<<64,             256>>>(w1, wa1, w2, wa2, g1, b1, m1, v1);
    k1_conv1x1  <<<dim3(2, 49, 2), 256>>>(x);
    k2_adder1x1 <<<dim3(2, 49, 2), 256>>>();
    k3x3<false> <<<dim3(49, 6),    256>>>();
    ky          <<<784,            128>>>();
    k3x3<true>  <<<dim3(49, 6),    256>>>();
    kepi        <<<784,            128>>>(x, g2, b2, m2, v2, out);
}

// round 8
// speedup vs baseline: 1.0206x; 1.0206x over previous
#include <cuda_runtime.h>

#define CIN  128
#define PP   784          // 28*28
#define NPIX 3136         // 4*784
typedef unsigned long long ull;

// ---------------- scratch (device globals; no allocation) ----------------
__device__ __align__(16) float g_y1p[2][CIN * NPIX];  // conv1x1 ci-half partials
__device__ __align__(16) float g_s1p[2][CIN * NPIX];  // adder1x1 ci-half partial L1 sums
__device__ __align__(16) float g_p3 [6][CIN * NPIX];  // conv3x3 (kh,ciHalf) partials
__device__ __align__(16) float g_y3 [CIN * NPIX];     // conv3x3 combined
__device__ __align__(16) float g_p4 [6][CIN * NPIX];  // adder3x3 partials (+S)
// transposed weights: [ci][co]
__device__ __align__(16) float g_w1t [CIN * CIN];
__device__ __align__(16) float g_wa1t[CIN * CIN];
__device__ __align__(16) float g_w2t [9][CIN * CIN];
__device__ __align__(16) float g_wa2t[9][CIN * CIN];
// BN1 folded params
__device__ float g_sc1[CIN], g_sh1[CIN];

// ---------------- packed f32x2 helpers -----------------------------------
__device__ __forceinline__ ull fma2(ull a, ull b, ull c) {
    ull d; asm("fma.rn.f32x2 %0, %1, %2, %3;" : "=l"(d) : "l"(a), "l"(b), "l"(c)); return d;
}
__device__ __forceinline__ ull add2(ull a, ull b) {
    ull d; asm("add.rn.f32x2 %0, %1, %2;" : "=l"(d) : "l"(a), "l"(b)); return d;
}
__device__ __forceinline__ ull dup2(float w) {
    ull d; asm("mov.b64 %0, {%1, %1};" : "=l"(d) : "f"(w)); return d;
}
#define NEG1X2 0xBF800000BF800000ULL
#define ABSM   0x7FFFFFFF7FFFFFFFULL

// =========================================================================
// kprep: transpose weights; fold BN1.
// =========================================================================
__global__ __launch_bounds__(256) void kprep(const float* __restrict__ w1,
                                             const float* __restrict__ wa1,
                                             const float* __restrict__ w2,
                                             const float* __restrict__ wa2,
                                             const float* __restrict__ g1,
                                             const float* __restrict__ b1,
                                             const float* __restrict__ m1,
                                             const float* __restrict__ v1) {
    int i = blockIdx.x * 256 + threadIdx.x;     // 64 blocks -> 16384
    int ci = i >> 7, co = i & 127;
    g_w1t [ci * CIN + co] = w1 [co * CIN + ci];
    g_wa1t[ci * CIN + co] = wa1[co * CIN + ci];
#pragma unroll
    for (int t = 0; t < 9; t++) {
        g_w2t [t][ci * CIN + co] = w2 [(co * CIN + ci) * 9 + t];
        g_wa2t[t][ci * CIN + co] = wa2[(co * CIN + ci) * 9 + t];
    }
    if (blockIdx.x == 0 && threadIdx.x < CIN) {
        int c = threadIdx.x;
        float sc = g1[c] / sqrtf(v1[c] + 1e-5f);
        g_sc1[c] = sc;
        g_sh1[c] = b1[c] - m1[c] * sc;
    }
}

// =========================================================================
// k1: conv1x1 ci-half partial. grid (2,49,2). CTA 64co x 64px, tile 4x4.
// (unchanged from R5 baseline)
// =========================================================================
__global__ __launch_bounds__(256) void k1_conv1x1(const float* __restrict__ x) {
    __shared__ __align__(16) float  sA[2][16][64];
    __shared__ __align__(16) float2 sW[2][16][64];
    const int tid = threadIdx.x;
    const int col = tid & 15, row = tid >> 4;
    const int coBase = blockIdx.x * 64;
    const int qBase  = blockIdx.y * 64;
    const int ciBase = blockIdx.z * 64;

    ull acc[4][2];
#pragma unroll
    for (int i = 0; i < 4; i++) { acc[i][0] = 0; acc[i][1] = 0; }

    float aReg[4], wReg[4];
    auto ldg = [&](int s) {
        int ci0 = ciBase + (s << 4);
#pragma unroll
        for (int k = 0; k < 4; k++) {
            int e = k * 256 + tid;
            int q = qBase + (e & 63);
            int n = q / PP, p = q - n * PP;
            aReg[k] = x[(n * CIN + ci0 + (e >> 6)) * PP + p];
        }
#pragma unroll
        for (int k = 0; k < 4; k++) {
            int e = k * 256 + tid;
            wReg[k] = g_w1t[(ci0 + (e >> 6)) * CIN + coBase + (e & 63)];
        }
    };
    auto sts = [&](int b) {
#pragma unroll
        for (int k = 0; k < 4; k++) { int e = k * 256 + tid; sA[b][e >> 6][e & 63] = aReg[k]; }
#pragma unroll
        for (int k = 0; k < 4; k++) { int e = k * 256 + tid; sW[b][e >> 6][e & 63] = make_float2(wReg[k], wReg[k]); }
    };

    ldg(0); sts(0); __syncthreads();
    for (int s = 0; s < 4; s++) {
        int b = s & 1;
        if (s < 3) ldg(s + 1);
#pragma unroll
        for (int ci = 0; ci < 16; ci++) {
            ulonglong2 av = *(const ulonglong2*)&sA[b][ci][col * 4];
            ulonglong2 wp = *(const ulonglong2*)&sW[b][ci][row * 4];
            ulonglong2 wq = *(const ulonglong2*)&sW[b][ci][row * 4 + 2];
            acc[0][0] = fma2(wp.x, av.x, acc[0][0]); acc[0][1] = fma2(wp.x, av.y, acc[0][1]);
            acc[1][0] = fma2(wp.y, av.x, acc[1][0]); acc[1][1] = fma2(wp.y, av.y, acc[1][1]);
            acc[2][0] = fma2(wq.x, av.x, acc[2][0]); acc[2][1] = fma2(wq.x, av.y, acc[2][1]);
            acc[3][0] = fma2(wq.y, av.x, acc[3][0]); acc[3][1] = fma2(wq.y, av.y, acc[3][1]);
        }
        if (s < 3) sts(b ^ 1);
        __syncthreads();
    }
    const int q = qBase + col * 4;
    float* __restrict__ out = g_y1p[blockIdx.z];
#pragma unroll
    for (int i = 0; i < 4; i++) {
        int co = coBase + row * 4 + i;
        *(ull*)&out[co * NPIX + q]     = acc[i][0];
        *(ull*)&out[co * NPIX + q + 2] = acc[i][1];
    }
}

// =========================================================================
// k2: adder1x1 ci-half partial L1 sums. (unchanged from R5 baseline)
// =========================================================================
__global__ __launch_bounds__(256) void k2_adder1x1() {
    __shared__ __align__(16) float  sA[2][16][64];
    __shared__ __align__(16) float2 sW[2][16][64];
    const int tid = threadIdx.x;
    const int col = tid & 15, row = tid >> 4;
    const int coBase = blockIdx.x * 64;
    const int qBase  = blockIdx.y * 64;
    const int ciBase = blockIdx.z * 64;

    ull acc[4][2];
#pragma unroll
    for (int i = 0; i < 4; i++) { acc[i][0] = 0; acc[i][1] = 0; }

    float aReg[4], wReg[4];
    auto ldg = [&](int s) {
        int ci0 = ciBase + (s << 4);
#pragma unroll
        for (int k = 0; k < 4; k++) {
            int e = k * 256 + tid;
            int off = (ci0 + (e >> 6)) * NPIX + qBase + (e & 63);
            aReg[k] = g_y1p[0][off] + g_y1p[1][off];
        }
#pragma unroll
        for (int k = 0; k < 4; k++) {
            int e = k * 256 + tid;
            wReg[k] = g_wa1t[(ci0 + (e >> 6)) * CIN + coBase + (e & 63)];
        }
    };
    auto sts = [&](int b) {
#pragma unroll
        for (int k = 0; k < 4; k++) { int e = k * 256 + tid; sA[b][e >> 6][e & 63] = aReg[k]; }
#pragma unroll
        for (int k = 0; k < 4; k++) { int e = k * 256 + tid; sW[b][e >> 6][e & 63] = make_float2(wReg[k], wReg[k]); }
    };

    ldg(0); sts(0); __syncthreads();
    for (int s = 0; s < 4; s++) {
        int b = s & 1;
        if (s < 3) ldg(s + 1);
#pragma unroll
        for (int ci = 0; ci < 16; ci++) {
            ulonglong2 av = *(const ulonglong2*)&sA[b][ci][col * 4];
            ulonglong2 wp = *(const ulonglong2*)&sW[b][ci][row * 4];
            ulonglong2 wq = *(const ulonglong2*)&sW[b][ci][row * 4 + 2];
            acc[0][0] = add2(acc[0][0], fma2(wp.x, NEG1X2, av.x) & ABSM);
            acc[0][1] = add2(acc[0][1], fma2(wp.x, NEG1X2, av.y) & ABSM);
            acc[1][0] = add2(acc[1][0], fma2(wp.y, NEG1X2, av.x) & ABSM);
            acc[1][1] = add2(acc[1][1], fma2(wp.y, NEG1X2, av.y) & ABSM);
            acc[2][0] = add2(acc[2][0], fma2(wq.x, NEG1X2, av.x) & ABSM);
            acc[2][1] = add2(acc[2][1], fma2(wq.x, NEG1X2, av.y) & ABSM);
            acc[3][0] = add2(acc[3][0], fma2(wq.y, NEG1X2, av.x) & ABSM);
            acc[3][1] = add2(acc[3][1], fma2(wq.y, NEG1X2, av.y) & ABSM);
        }
        if (s < 3) sts(b ^ 1);
        __syncthreads();
    }
    const int q = qBase + col * 4;
    float* __restrict__ out = g_s1p[blockIdx.z];
#pragma unroll
    for (int i = 0; i < 4; i++) {
        int co = coBase + row * 4 + i;
        *(ull*)&out[co * NPIX + q]     = acc[i][0];
        *(ull*)&out[co * NPIX + q + 2] = acc[i][1];
    }
}

// =========================================================================
// k3/k4: 3x3 conv / adder. CTA 64co x 64px, 128 thr, tile 4co x 8px.
// col = tid&7 (8px), row = tid>>3 (16 rows of 4co). Warp = 4 rows x 8 cols:
// A LDS.128 = 8 distinct lines (1 wf), W = plain-float LDS.128 over 4 lines
// (broadcast, 1 wf); weight duplication to {w,w} in registers (mov.b64).
// grid (2, 49, 6) = 588 CTAs of 4 warps. Conv fuses BN1+ReLU at staging.
// =========================================================================
template <bool ADDER>
__global__ __launch_bounds__(128) void k3x3() {
    __shared__ __align__(16) float sA[2][16][64];
    __shared__ __align__(16) float sW[2][16][64];
    __shared__ int sIdx[3][64];
    __shared__ float2 sBN[64];

    const int tid = threadIdx.x;
    const int col = tid & 7, row = tid >> 3;
    const int coBase = blockIdx.x * 64;
    const int qBase  = blockIdx.y * 64;
    const int kh     = blockIdx.z >> 1;
    const int ciBase = (blockIdx.z & 1) * 64;

    if (tid < 64) {
        int q = qBase + tid;
        int n = q / PP, p = q - n * PP;
        int h = p / 28, w = p - h * 28;
#pragma unroll
        for (int kw = 0; kw < 3; kw++) {
            int hh = h + kh - 1, ww = w + kw - 1;
            sIdx[kw][tid] = ((unsigned)hh < 28u && (unsigned)ww < 28u)
                          ? (n * PP + hh * 28 + ww) : -1;
        }
        if (!ADDER) sBN[tid] = make_float2(g_sc1[ciBase + tid], g_sh1[ciBase + tid]);
    }
    __syncthreads();

    ull acc[4][4];
#pragma unroll
    for (int i = 0; i < 4; i++)
#pragma unroll
        for (int j = 0; j < 4; j++) acc[i][j] = 0;

    const float* __restrict__ wsrc = ADDER ? &g_wa2t[0][0] : &g_w2t[0][0];

    float aReg[8], wReg[8];
    auto ldg = [&](int s) {
        int kw = s >> 2, ciOff = (s & 3) << 4;
#pragma unroll
        for (int k = 0; k < 8; k++) {               // A: 64px x 16ci / 128thr
            int e = k * 128 + tid;
            int ciL = ciOff + (e >> 6);
            int idx = sIdx[kw][e & 63];
            float v = 0.f;
            if (idx >= 0) {
                int off = (ciBase + ciL) * NPIX + idx;
                if (ADDER) {
                    v = g_y3[off];
                } else {
                    float ssum = g_s1p[0][off] + g_s1p[1][off];
                    float2 bn = sBN[ciL];
                    v = fmaxf(fmaf(-ssum, bn.x, bn.y), 0.f);
                }
            }
            aReg[k] = v;
        }
        const float* __restrict__ wslice = wsrc + (kh * 3 + kw) * (CIN * CIN);
#pragma unroll
        for (int k = 0; k < 8; k++) {               // W: 64co x 16ci / 128thr
            int e = k * 128 + tid;
            wReg[k] = wslice[(ciBase + ciOff + (e >> 6)) * CIN + coBase + (e & 63)];
        }
    };
    auto sts = [&](int b) {
#pragma unroll
        for (int k = 0; k < 8; k++) { int e = k * 128 + tid; sA[b][e >> 6][e & 63] = aReg[k]; }
#pragma unroll
        for (int k = 0; k < 8; k++) { int e = k * 128 + tid; sW[b][e >> 6][e & 63] = wReg[k]; }
    };

    ldg(0); sts(0); __syncthreads();
    for (int s = 0; s < 12; s++) {
        int b = s & 1;
        if (s < 11) ldg(s + 1);
#pragma unroll
        for (int ci = 0; ci < 16; ci++) {
            ulonglong2 a01 = *(const ulonglong2*)&sA[b][ci][col * 8];
            ulonglong2 a23 = *(const ulonglong2*)&sA[b][ci][col * 8 + 4];
            float4 w4 = *(const float4*)&sW[b][ci][row * 4];
            ull w0 = dup2(w4.x), w1 = dup2(w4.y), w2 = dup2(w4.z), w3 = dup2(w4.w);
            if (ADDER) {
                acc[0][0] = add2(acc[0][0], fma2(w0, NEG1X2, a01.x) & ABSM);
                acc[0][1] = add2(acc[0][1], fma2(w0, NEG1X2, a01.y) & ABSM);
                acc[0][2] = add2(acc[0][2], fma2(w0, NEG1X2, a23.x) & ABSM);
                acc[0][3] = add2(acc[0][3], fma2(w0, NEG1X2, a23.y) & ABSM);
                acc[1][0] = add2(acc[1][0], fma2(w1, NEG1X2, a01.x) & ABSM);
                acc[1][1] = add2(acc[1][1], fma2(w1, NEG1X2, a01.y) & ABSM);
                acc[1][2] = add2(acc[1][2], fma2(w1, NEG1X2, a23.x) & ABSM);
                acc[1][3] = add2(acc[1][3], fma2(w1, NEG1X2, a23.y) & ABSM);
                acc[2][0] = add2(acc[2][0], fma2(w2, NEG1X2, a01.x) & ABSM);
                acc[2][1] = add2(acc[2][1], fma2(w2, NEG1X2, a01.y) & ABSM);
                acc[2][2] = add2(acc[2][2], fma2(w2, NEG1X2, a23.x) & ABSM);
                acc[2][3] = add2(acc[2][3], fma2(w2, NEG1X2, a23.y) & ABSM);
                acc[3][0] = add2(acc[3][0], fma2(w3, NEG1X2, a01.x) & ABSM);
                acc[3][1] = add2(acc[3][1], fma2(w3, NEG1X2, a01.y) & ABSM);
                acc[3][2] = add2(acc[3][2], fma2(w3, NEG1X2, a23.x) & ABSM);
                acc[3][3] = add2(acc[3][3], fma2(w3, NEG1X2, a23.y) & ABSM);
            } else {
                acc[0][0] = fma2(w0, a01.x, acc[0][0]);
                acc[0][1] = fma2(w0, a01.y, acc[0][1]);
                acc[0][2] = fma2(w0, a23.x, acc[0][2]);
                acc[0][3] = fma2(w0, a23.y, acc[0][3]);
                acc[1][0] = fma2(w1, a01.x, acc[1][0]);
                acc[1][1] = fma2(w1, a01.y, acc[1][1]);
                acc[1][2] = fma2(w1, a23.x, acc[1][2]);
                acc[1][3] = fma2(w1, a23.y, acc[1][3]);
                acc[2][0] = fma2(w2, a01.x, acc[2][0]);
                acc[2][1] = fma2(w2, a01.y, acc[2][1]);
                acc[2][2] = fma2(w2, a23.x, acc[2][2]);
                acc[2][3] = fma2(w2, a23.y, acc[2][3]);
                acc[3][0] = fma2(w3, a01.x, acc[3][0]);
                acc[3][1] = fma2(w3, a01.y, acc[3][1]);
                acc[3][2] = fma2(w3, a23.x, acc[3][2]);
                acc[3][3] = fma2(w3, a23.y, acc[3][3]);
            }
        }
        if (s < 11) sts(b ^ 1);
        __syncthreads();
    }
    const int q = qBase + col * 8;
    float* __restrict__ out = ADDER ? g_p4[blockIdx.z] : g_p3[blockIdx.z];
#pragma unroll
    for (int i = 0; i < 4; i++) {
        int co = coBase + row * 4 + i;
#pragma unroll
        for (int j = 0; j < 4; j++)
            *(ull*)&out[co * NPIX + q + 2 * j] = acc[i][j];
    }
}

// ky: y3 = sum of 6 conv partials. 784 blocks x 128 thr, one float4 each.
__global__ __launch_bounds__(128) void ky() {
    int i = (blockIdx.x * 128 + threadIdx.x) * 4;
    float4 s = *(const float4*)&g_p3[0][i];
#pragma unroll
    for (int t = 1; t < 6; t++) {
        float4 a = *(const float4*)&g_p3[t][i];
        s.x += a.x; s.y += a.y; s.z += a.z; s.w += a.w;
    }
    *(float4*)&g_y3[i] = s;
}

// Epilogue: out = relu( relu(bn2(-S)) + x ), S = sum of 6 adder partials.
__device__ __forceinline__ float epi1(float S, float xv, float scale, float shift) {
    float v = fmaxf(fmaf(-S, scale, shift), 0.f);
    return fmaxf(v + xv, 0.f);
}
__global__ __launch_bounds__(128) void kepi(const float* __restrict__ x,
                                             const float* __restrict__ g2,
                                             const float* __restrict__ b2,
                                             const float* __restrict__ m2,
                                             const float* __restrict__ v2,
                                             float* __restrict__ out) {
    int base = (blockIdx.x * 128 + threadIdx.x) * 4;
    int c = base / NPIX;
    int q = base - c * NPIX;
    int n = q / PP, p = q - n * PP;
    float scale = g2[c] / sqrtf(v2[c] + 1e-5f);
    float shift = b2[c] - m2[c] * scale;
    float4 s = *(const float4*)&g_p4[0][base];
#pragma unroll
    for (int t = 1; t < 6; t++) {
        float4 a = *(const float4*)&g_p4[t][base];
        s.x += a.x; s.y += a.y; s.z += a.z; s.w += a.w;
    }
    int xi = (n * CIN + c) * PP + p;
    float4 xr = *(const float4*)&x[xi];
    float4 r;
    r.x = epi1(s.x, xr.x, scale, shift);
    r.y = epi1(s.y, xr.y, scale, shift);
    r.z = epi1(s.z, xr.z, scale, shift);
    r.w = epi1(s.w, xr.w, scale, shift);
    *(float4*)&out[xi] = r;
}

// =========================================================================
extern "C" void kernel_launch(void* const* d_in, const int* in_sizes, int n_in,
                              void* d_out, int out_size) {
    const float* x   = (const float*)d_in[0];
    const float* w1  = (const float*)d_in[1];
    const float* wa1 = (const float*)d_in[2];
    const float* g1  = (const float*)d_in[3];
    const float* b1  = (const float*)d_in[4];
    const float* m1  = (const float*)d_in[5];
    const float* v1  = (const float*)d_in[6];
    const float* w2  = (const float*)d_in[7];
    const float* wa2 = (const float*)d_in[8];
    const float* g2  = (const float*)d_in[9];
    const float* b2  = (const float*)d_in[10];
    const float* m2  = (const float*)d_in[11];
    const float* v2  = (const float*)d_in[12];
    float* out = (float*)d_out;

    kprep       <<<64,             256>>>(w1, wa1, w2, wa2, g1, b1, m1, v1);
    k1_conv1x1  <<<dim3(2, 49, 2), 256>>>(x);
    k2_adder1x1 <<<dim3(2, 49, 2), 256>>>();
    k3x3<false> <<<dim3(2, 49, 6), 128>>>();
    ky          <<<784,            128>>>();
    k3x3<true>  <<<dim3(2, 49, 6), 128>>>();
    kepi        <<<784,            128>>>(x, g2, b2, m2, v2, out);
}

// round 9
// speedup vs baseline: 1.2241x; 1.1994x over previous
#include <cuda_runtime.h>

#define CIN  128
#define PP   784          // 28*28
#define NPIX 3136         // 4*784
#define PIMG 900          // 30*30 padded image
#define PADN 3600         // 4*900 per channel
typedef unsigned long long ull;

// ---------------- scratch (device globals; no allocation) ----------------
__device__ __align__(16) float g_y1p[2][CIN * NPIX];  // conv1x1 ci-half partials
__device__ __align__(16) float g_s1p[2][CIN * NPIX];  // adder1x1 ci-half partial L1 sums
__device__ __align__(16) float g_zp [CIN * PADN];     // z  (bn1+relu), zero-padded 30x30
__device__ __align__(16) float g_p3 [6][CIN * NPIX];  // conv3x3 (kh,ciHalf) partials
__device__ __align__(16) float g_y3p[CIN * PADN];     // conv3x3 combined, zero-padded
__device__ __align__(16) float g_p4 [6][CIN * NPIX];  // adder3x3 partials (+S)
// transposed weights: [ci][co]
__device__ __align__(16) float g_w1t [CIN * CIN];
__device__ __align__(16) float g_wa1t[CIN * CIN];
__device__ __align__(16) float g_w2t [9][CIN * CIN];
__device__ __align__(16) float g_wa2t[9][CIN * CIN];
// BN1 folded params
__device__ float g_sc1[CIN], g_sh1[CIN];

// ---------------- packed f32x2 helpers -----------------------------------
__device__ __forceinline__ ull fma2(ull a, ull b, ull c) {
    ull d; asm("fma.rn.f32x2 %0, %1, %2, %3;" : "=l"(d) : "l"(a), "l"(b), "l"(c)); return d;
}
__device__ __forceinline__ ull add2(ull a, ull b) {
    ull d; asm("add.rn.f32x2 %0, %1, %2;" : "=l"(d) : "l"(a), "l"(b)); return d;
}
__device__ __forceinline__ ull dup2(float w) {
    ull d; asm("mov.b64 %0, {%1, %1};" : "=l"(d) : "f"(w)); return d;
}
#define NEG1X2 0xBF800000BF800000ULL
#define ABSM   0x7FFFFFFF7FFFFFFFULL

// =========================================================================
// kprep: transpose weights; fold BN1.
// =========================================================================
__global__ __launch_bounds__(256) void kprep(const float* __restrict__ w1,
                                             const float* __restrict__ wa1,
                                             const float* __restrict__ w2,
                                             const float* __restrict__ wa2,
                                             const float* __restrict__ g1,
                                             const float* __restrict__ b1,
                                             const float* __restrict__ m1,
                                             const float* __restrict__ v1) {
    int i = blockIdx.x * 256 + threadIdx.x;     // 64 blocks -> 16384
    int ci = i >> 7, co = i & 127;
    g_w1t [ci * CIN + co] = w1 [co * CIN + ci];
    g_wa1t[ci * CIN + co] = wa1[co * CIN + ci];
#pragma unroll
    for (int t = 0; t < 9; t++) {
        g_w2t [t][ci * CIN + co] = w2 [(co * CIN + ci) * 9 + t];
        g_wa2t[t][ci * CIN + co] = wa2[(co * CIN + ci) * 9 + t];
    }
    if (blockIdx.x == 0 && threadIdx.x < CIN) {
        int c = threadIdx.x;
        float sc = g1[c] / sqrtf(v1[c] + 1e-5f);
        g_sc1[c] = sc;
        g_sh1[c] = b1[c] - m1[c] * sc;
    }
}

// =========================================================================
// k1: conv1x1 ci-half partial. grid (2,49,2). CTA 64co x 64px, tile 4x4.
// =========================================================================
__global__ __launch_bounds__(256) void k1_conv1x1(const float* __restrict__ x) {
    __shared__ __align__(16) float  sA[2][16][64];
    __shared__ __align__(16) float2 sW[2][16][64];
    const int tid = threadIdx.x;
    const int col = tid & 15, row = tid >> 4;
    const int coBase = blockIdx.x * 64;
    const int qBase  = blockIdx.y * 64;
    const int ciBase = blockIdx.z * 64;

    ull acc[4][2];
#pragma unroll
    for (int i = 0; i < 4; i++) { acc[i][0] = 0; acc[i][1] = 0; }

    float aReg[4], wReg[4];
    auto ldg = [&](int s) {
        int ci0 = ciBase + (s << 4);
#pragma unroll
        for (int k = 0; k < 4; k++) {
            int e = k * 256 + tid;
            int q = qBase + (e & 63);
            int n = q / PP, p = q - n * PP;
            aReg[k] = x[(n * CIN + ci0 + (e >> 6)) * PP + p];
        }
#pragma unroll
        for (int k = 0; k < 4; k++) {
            int e = k * 256 + tid;
            wReg[k] = g_w1t[(ci0 + (e >> 6)) * CIN + coBase + (e & 63)];
        }
    };
    auto sts = [&](int b) {
#pragma unroll
        for (int k = 0; k < 4; k++) { int e = k * 256 + tid; sA[b][e >> 6][e & 63] = aReg[k]; }
#pragma unroll
        for (int k = 0; k < 4; k++) { int e = k * 256 + tid; sW[b][e >> 6][e & 63] = make_float2(wReg[k], wReg[k]); }
    };

    ldg(0); sts(0); __syncthreads();
    for (int s = 0; s < 4; s++) {
        int b = s & 1;
        if (s < 3) ldg(s + 1);
#pragma unroll
        for (int ci = 0; ci < 16; ci++) {
            ulonglong2 av = *(const ulonglong2*)&sA[b][ci][col * 4];
            ulonglong2 wp = *(const ulonglong2*)&sW[b][ci][row * 4];
            ulonglong2 wq = *(const ulonglong2*)&sW[b][ci][row * 4 + 2];
            acc[0][0] = fma2(wp.x, av.x, acc[0][0]); acc[0][1] = fma2(wp.x, av.y, acc[0][1]);
            acc[1][0] = fma2(wp.y, av.x, acc[1][0]); acc[1][1] = fma2(wp.y, av.y, acc[1][1]);
            acc[2][0] = fma2(wq.x, av.x, acc[2][0]); acc[2][1] = fma2(wq.x, av.y, acc[2][1]);
            acc[3][0] = fma2(wq.y, av.x, acc[3][0]); acc[3][1] = fma2(wq.y, av.y, acc[3][1]);
        }
        if (s < 3) sts(b ^ 1);
        __syncthreads();
    }
    const int q = qBase + col * 4;
    float* __restrict__ out = g_y1p[blockIdx.z];
#pragma unroll
    for (int i = 0; i < 4; i++) {
        int co = coBase + row * 4 + i;
        *(ull*)&out[co * NPIX + q]     = acc[i][0];
        *(ull*)&out[co * NPIX + q + 2] = acc[i][1];
    }
}

// =========================================================================
// k2: adder1x1 ci-half partial L1 sums.
// =========================================================================
__global__ __launch_bounds__(256) void k2_adder1x1() {
    __shared__ __align__(16) float  sA[2][16][64];
    __shared__ __align__(16) float2 sW[2][16][64];
    const int tid = threadIdx.x;
    const int col = tid & 15, row = tid >> 4;
    const int coBase = blockIdx.x * 64;
    const int qBase  = blockIdx.y * 64;
    const int ciBase = blockIdx.z * 64;

    ull acc[4][2];
#pragma unroll
    for (int i = 0; i < 4; i++) { acc[i][0] = 0; acc[i][1] = 0; }

    float aReg[4], wReg[4];
    auto ldg = [&](int s) {
        int ci0 = ciBase + (s << 4);
#pragma unroll
        for (int k = 0; k < 4; k++) {
            int e = k * 256 + tid;
            int off = (ci0 + (e >> 6)) * NPIX + qBase + (e & 63);
            aReg[k] = g_y1p[0][off] + g_y1p[1][off];
        }
#pragma unroll
        for (int k = 0; k < 4; k++) {
            int e = k * 256 + tid;
            wReg[k] = g_wa1t[(ci0 + (e >> 6)) * CIN + coBase + (e & 63)];
        }
    };
    auto sts = [&](int b) {
#pragma unroll
        for (int k = 0; k < 4; k++) { int e = k * 256 + tid; sA[b][e >> 6][e & 63] = aReg[k]; }
#pragma unroll
        for (int k = 0; k < 4; k++) { int e = k * 256 + tid; sW[b][e >> 6][e & 63] = make_float2(wReg[k], wReg[k]); }
    };

    ldg(0); sts(0); __syncthreads();
    for (int s = 0; s < 4; s++) {
        int b = s & 1;
        if (s < 3) ldg(s + 1);
#pragma unroll
        for (int ci = 0; ci < 16; ci++) {
            ulonglong2 av = *(const ulonglong2*)&sA[b][ci][col * 4];
            ulonglong2 wp = *(const ulonglong2*)&sW[b][ci][row * 4];
            ulonglong2 wq = *(const ulonglong2*)&sW[b][ci][row * 4 + 2];
            acc[0][0] = add2(acc[0][0], fma2(wp.x, NEG1X2, av.x) & ABSM);
            acc[0][1] = add2(acc[0][1], fma2(wp.x, NEG1X2, av.y) & ABSM);
            acc[1][0] = add2(acc[1][0], fma2(wp.y, NEG1X2, av.x) & ABSM);
            acc[1][1] = add2(acc[1][1], fma2(wp.y, NEG1X2, av.y) & ABSM);
            acc[2][0] = add2(acc[2][0], fma2(wq.x, NEG1X2, av.x) & ABSM);
            acc[2][1] = add2(acc[2][1], fma2(wq.x, NEG1X2, av.y) & ABSM);
            acc[3][0] = add2(acc[3][0], fma2(wq.y, NEG1X2, av.x) & ABSM);
            acc[3][1] = add2(acc[3][1], fma2(wq.y, NEG1X2, av.y) & ABSM);
        }
        if (s < 3) sts(b ^ 1);
        __syncthreads();
    }
    const int q = qBase + col * 4;
    float* __restrict__ out = g_s1p[blockIdx.z];
#pragma unroll
    for (int i = 0; i < 4; i++) {
        int co = coBase + row * 4 + i;
        *(ull*)&out[co * NPIX + q]     = acc[i][0];
        *(ull*)&out[co * NPIX + q + 2] = acc[i][1];
    }
}

// =========================================================================
// kz: z = relu(bn1(-(s0+s1))) written into zero-padded layout [c][n][30][30].
// Borders are never written (device globals start zero, stay zero).
// 784 blocks x 128 thr; each thread: one (c,n,h,chunk-of-4w).
// =========================================================================
__global__ __launch_bounds__(128) void kz() {
    int e = blockIdx.x * 128 + threadIdx.x;     // 100352
    int chunk = e % 7;
    int rowid = e / 7;                          // (c,n,h)
    int h = rowid % 28;
    int n = (rowid / 28) & 3;
    int c = rowid / 112;
    int qo = c * NPIX + n * PP + h * 28 + chunk * 4;
    float4 a = *(const float4*)&g_s1p[0][qo];
    float4 b = *(const float4*)&g_s1p[1][qo];
    float sc = g_sc1[c], sh = g_sh1[c];
    int po = c * PADN + n * PIMG + (h + 1) * 30 + 1 + chunk * 4;
    g_zp[po]     = fmaxf(fmaf(-(a.x + b.x), sc, sh), 0.f);
    g_zp[po + 1] = fmaxf(fmaf(-(a.y + b.y), sc, sh), 0.f);
    g_zp[po + 2] = fmaxf(fmaf(-(a.z + b.z), sc, sh), 0.f);
    g_zp[po + 3] = fmaxf(fmaf(-(a.w + b.w), sc, sh), 0.f);
}

// =========================================================================
// k3/k4: 3x3 conv / adder. CTA 128co x 64px, 128 thr, tile 8co x 8px.
// col=tid&7 (8px), row=tid>>3 (16 x 8co). grid (49, 6), y = kh*2 + ciHalf.
// A: branch-free scalar LDG from padded input, single sIdx table (+kw).
// W: float4 LDG/STS. Compute: per ci 4 LDS wf vs 16 fma-cyc.
// =========================================================================
template <bool ADDER>
__global__ __launch_bounds__(128) void k3x3() {
    __shared__ __align__(16) float sA[2][16][64];
    __shared__ __align__(16) float sW[2][16][128];
    __shared__ int sIdx[64];

    const int tid = threadIdx.x;
    const int col = tid & 7, row = tid >> 3;
    const int qBase  = blockIdx.x * 64;
    const int kh     = blockIdx.y >> 1;
    const int ciBase = (blockIdx.y & 1) * 64;

    if (tid < 64) {
        int q = qBase + tid;
        int n = q / PP, p = q - n * PP;
        int h = p / 28, w = p - h * 28;
        sIdx[tid] = n * PIMG + (h + kh) * 30 + w;   // +kw at load; always valid
    }
    __syncthreads();

    ull acc[8][4];
#pragma unroll
    for (int i = 0; i < 8; i++)
#pragma unroll
        for (int j = 0; j < 4; j++) acc[i][j] = 0;

    const float* __restrict__ in   = ADDER ? g_y3p : g_zp;
    const float* __restrict__ wsrc = ADDER ? &g_wa2t[0][0] : &g_w2t[0][0];

    float aReg[8];
    float4 wReg[4];
    auto ldg = [&](int s) {
        int kw = s >> 2, ciOff = (s & 3) << 4;
        int cB = ciBase + ciOff;
#pragma unroll
        for (int k = 0; k < 8; k++) {               // A: 16ci x 64px scalar
            int e = k * 128 + tid;
            aReg[k] = in[(cB + (e >> 6)) * PADN + sIdx[e & 63] + kw];
        }
        const float* __restrict__ wslice = wsrc + (kh * 3 + kw) * (CIN * CIN);
#pragma unroll
        for (int k = 0; k < 4; k++) {               // W: 16ci x 128co float4
            int e4 = (k * 128 + tid) * 4;
            wReg[k] = *(const float4*)&wslice[(cB + (e4 >> 7)) * CIN + (e4 & 127)];
        }
    };
    auto sts = [&](int b) {
#pragma unroll
        for (int k = 0; k < 8; k++) { int e = k * 128 + tid; sA[b][e >> 6][e & 63] = aReg[k]; }
#pragma unroll
        for (int k = 0; k < 4; k++) { int e4 = (k * 128 + tid) * 4; *(float4*)&sW[b][e4 >> 7][e4 & 127] = wReg[k]; }
    };

    ldg(0); sts(0); __syncthreads();
    for (int s = 0; s < 12; s++) {
        int b = s & 1;
        if (s < 11) ldg(s + 1);
#pragma unroll
        for (int ci = 0; ci < 16; ci++) {
            ulonglong2 a01 = *(const ulonglong2*)&sA[b][ci][col * 8];
            ulonglong2 a23 = *(const ulonglong2*)&sA[b][ci][col * 8 + 4];
            float4 wa = *(const float4*)&sW[b][ci][row * 8];
            float4 wb = *(const float4*)&sW[b][ci][row * 8 + 4];
            float wf[8] = {wa.x, wa.y, wa.z, wa.w, wb.x, wb.y, wb.z, wb.w};
#pragma unroll
            for (int i = 0; i < 8; i++) {
                ull wd = dup2(wf[i]);
                if (ADDER) {
                    acc[i][0] = add2(acc[i][0], fma2(wd, NEG1X2, a01.x) & ABSM);
                    acc[i][1] = add2(acc[i][1], fma2(wd, NEG1X2, a01.y) & ABSM);
                    acc[i][2] = add2(acc[i][2], fma2(wd, NEG1X2, a23.x) & ABSM);
                    acc[i][3] = add2(acc[i][3], fma2(wd, NEG1X2, a23.y) & ABSM);
                } else {
                    acc[i][0] = fma2(wd, a01.x, acc[i][0]);
                    acc[i][1] = fma2(wd, a01.y, acc[i][1]);
                    acc[i][2] = fma2(wd, a23.x, acc[i][2]);
                    acc[i][3] = fma2(wd, a23.y, acc[i][3]);
                }
            }
        }
        if (s < 11) sts(b ^ 1);
        __syncthreads();
    }
    const int q = qBase + col * 8;
    float* __restrict__ out = ADDER ? g_p4[blockIdx.y] : g_p3[blockIdx.y];
#pragma unroll
    for (int i = 0; i < 8; i++) {
        int co = row * 8 + i;
#pragma unroll
        for (int j = 0; j < 4; j++)
            *(ull*)&out[co * NPIX + q + 2 * j] = acc[i][j];
    }
}

// =========================================================================
// ky: y3 = sum of 6 conv partials, written into padded layout.
// =========================================================================
__global__ __launch_bounds__(128) void ky() {
    int e = blockIdx.x * 128 + threadIdx.x;     // 100352
    int chunk = e % 7;
    int rowid = e / 7;
    int h = rowid % 28;
    int n = (rowid / 28) & 3;
    int c = rowid / 112;
    int qo = c * NPIX + n * PP + h * 28 + chunk * 4;
    float4 s = *(const float4*)&g_p3[0][qo];
#pragma unroll
    for (int t = 1; t < 6; t++) {
        float4 a = *(const float4*)&g_p3[t][qo];
        s.x += a.x; s.y += a.y; s.z += a.z; s.w += a.w;
    }
    int po = c * PADN + n * PIMG + (h + 1) * 30 + 1 + chunk * 4;
    g_y3p[po]     = s.x;
    g_y3p[po + 1] = s.y;
    g_y3p[po + 2] = s.z;
    g_y3p[po + 3] = s.w;
}

// Epilogue: out = relu( relu(bn2(-S)) + x ), S = sum of 6 adder partials.
__device__ __forceinline__ float epi1(float S, float xv, float scale, float shift) {
    float v = fmaxf(fmaf(-S, scale, shift), 0.f);
    return fmaxf(v + xv, 0.f);
}
__global__ __launch_bounds__(128) void kepi(const float* __restrict__ x,
                                             const float* __restrict__ g2,
                                             const float* __restrict__ b2,
                                             const float* __restrict__ m2,
                                             const float* __restrict__ v2,
                                             float* __restrict__ out) {
    int base = (blockIdx.x * 128 + threadIdx.x) * 4;
    int c = base / NPIX;
    int q = base - c * NPIX;
    int n = q / PP, p = q - n * PP;
    float scale = g2[c] / sqrtf(v2[c] + 1e-5f);
    float shift = b2[c] - m2[c] * scale;
    float4 s = *(const float4*)&g_p4[0][base];
#pragma unroll
    for (int t = 1; t < 6; t++) {
        float4 a = *(const float4*)&g_p4[t][base];
        s.x += a.x; s.y += a.y; s.z += a.z; s.w += a.w;
    }
    int xi = (n * CIN + c) * PP + p;
    float4 xr = *(const float4*)&x[xi];
    float4 r;
    r.x = epi1(s.x, xr.x, scale, shift);
    r.y = epi1(s.y, xr.y, scale, shift);
    r.z = epi1(s.z, xr.z, scale, shift);
    r.w = epi1(s.w, xr.w, scale, shift);
    *(float4*)&out[xi] = r;
}

// =========================================================================
extern "C" void kernel_launch(void* const* d_in, const int* in_sizes, int n_in,
                              void* d_out, int out_size) {
    const float* x   = (const float*)d_in[0];
    const float* w1  = (const float*)d_in[1];
    const float* wa1 = (const float*)d_in[2];
    const float* g1  = (const float*)d_in[3];
    const float* b1  = (const float*)d_in[4];
    const float* m1  = (const float*)d_in[5];
    const float* v1  = (const float*)d_in[6];
    const float* w2  = (const float*)d_in[7];
    const float* wa2 = (const float*)d_in[8];
    const float* g2  = (const float*)d_in[9];
    const float* b2  = (const float*)d_in[10];
    const float* m2  = (const float*)d_in[11];
    const float* v2  = (const float*)d_in[12];
    float* out = (float*)d_out;

    kprep       <<<64,             256>>>(w1, wa1, w2, wa2, g1, b1, m1, v1);
    k1_conv1x1  <<<dim3(2, 49, 2), 256>>>(x);
    k2_adder1x1 <<<dim3(2, 49, 2), 256>>>();
    kz          <<<784,            128>>>();
    k3x3<false> <<<dim3(49, 6),    128>>>();
    ky          <<<784,            128>>>();
    k3x3<true>  <<<dim3(49, 6),    128>>>();
    kepi        <<<784,            128>>>(x, g2, b2, m2, v2, out);
}